// round 5
// baseline (speedup 1.0000x reference)
#include <cuda_runtime.h>
#include <cuda_fp16.h>
#include <cstdint>

#define HW 128
#define CH 128
#define NB 8

// ---------------------------------------------------------------------------
// Device-global scratch
// ---------------------------------------------------------------------------
__device__ __align__(256) __half d_x16[(size_t)NB * HW * HW * CH];  // NHWC fp16
__device__ __align__(256) __half d_Wg[9 * 128 * 128];               // [tap][co][ci]
__device__ float d_Beff[128];

__constant__ int cJ[8][8] = {
  {0,1,2,3,4,5,6,7},{1,0,4,6,2,7,3,5},{2,4,0,5,1,3,7,6},{3,6,5,0,7,2,1,4},
  {4,2,1,7,0,6,5,3},{5,7,3,2,6,0,4,1},{6,3,7,1,5,4,0,2},{7,5,6,4,3,1,2,0}};
__constant__ float cS[8][8] = {
  { 1, 1, 1, 1,-1,-1,-1,-1},{ 1, 1,-1,-1, 1,-1, 1,-1},
  { 1, 1, 1,-1,-1, 1, 1, 1},{ 1, 1, 1, 1,-1,-1,-1,-1},
  { 1, 1,-1, 1, 1, 1,-1, 1},{ 1, 1, 1,-1,-1, 1, 1, 1},
  { 1, 1,-1,-1, 1,-1, 1,-1},{ 1, 1,-1, 1, 1, 1,-1, 1}};

__device__ __forceinline__ uint32_t smem_u32(const void* p) {
  uint32_t a;
  asm("{ .reg .u64 t; cvta.to.shared.u64 t, %1; cvt.u32.u64 %0, t; }"
      : "=r"(a) : "l"(p));
  return a;
}
__device__ __forceinline__ void cp16(uint32_t dst, const void* src) {
  asm volatile("cp.async.cg.shared.global [%0], [%1], 16;"
               :: "r"(dst), "l"(src) : "memory");
}
__device__ __forceinline__ void cp_commit() {
  asm volatile("cp.async.commit_group;" ::: "memory");
}
__device__ __forceinline__ void cp_wait1() {
  asm volatile("cp.async.wait_group 1;" ::: "memory");
}
__device__ __forceinline__ void cp_wait0() {
  asm volatile("cp.async.wait_group 0;" ::: "memory");
}

// ---------------------------------------------------------------------------
// Prepass 1: fp32 NCHW -> fp16 NHWC, coalesced both ways. CTA per (h, b).
// ---------------------------------------------------------------------------
#define XR 132                       // smem row stride in halves
__global__ void __launch_bounds__(256) xprep_kernel(const float* __restrict__ x) {
  __shared__ __align__(16) __half sm[128 * XR];
  const int h = blockIdx.x, b = blockIdx.y, tid = threadIdx.x;
  const float* xp = x + ((size_t)b * CH) * HW * HW + (size_t)h * HW;

  // Phase 1: 1024 tasks (ci, seg): read 64B contiguous, store [ci][w] halves.
#pragma unroll
  for (int i = 0; i < 4; ++i) {
    int t = tid + i * 256;
    int ci = t >> 3, seg = t & 7;
    const float4* src = (const float4*)(xp + (size_t)ci * HW * HW + seg * 16);
    float4 v0 = src[0], v1 = src[1], v2 = src[2], v3 = src[3];
    __half2* dst = (__half2*)(sm + ci * XR + seg * 16);
    dst[0] = __floats2half2_rn(v0.x, v0.y);
    dst[1] = __floats2half2_rn(v0.z, v0.w);
    dst[2] = __floats2half2_rn(v1.x, v1.y);
    dst[3] = __floats2half2_rn(v1.z, v1.w);
    dst[4] = __floats2half2_rn(v2.x, v2.y);
    dst[5] = __floats2half2_rn(v2.z, v2.w);
    dst[6] = __floats2half2_rn(v3.x, v3.y);
    dst[7] = __floats2half2_rn(v3.z, v3.w);
  }
  __syncthreads();

  // Phase 2: 2048 tasks; lane = w_lo<<4 | c8 for coalesced NHWC stores.
  __half* op = d_x16 + ((size_t)(b * HW + h)) * HW * CH;
#pragma unroll
  for (int i = 0; i < 8; ++i) {
    int t = tid + i * 256;
    int c8 = t & 15;
    int w = ((t >> 4) & 1) + ((t >> 5) << 1);
    __half hv[8];
#pragma unroll
    for (int jj = 0; jj < 8; ++jj)
      hv[jj] = sm[(c8 * 8 + jj) * XR + w];
    *(uint4*)(op + (size_t)w * CH + c8 * 8) = *(const uint4*)hv;
  }
}

// ---------------------------------------------------------------------------
// Prepass 2: fold signs into weights -> d_Wg[tap][co][ci] fp16; also bias.
// ---------------------------------------------------------------------------
__global__ void __launch_bounds__(256)
weff_kernel(const float* __restrict__ W, const float* __restrict__ bia) {
  int idx = blockIdx.x * 256 + threadIdx.x;
  if (blockIdx.x == 0 && threadIdx.x < 128) {
    int co = threadIdx.x, cout = co >> 3, m = co & 7;
    float s = 0.f;
#pragma unroll
    for (int k = 0; k < 8; k++) s += cS[m][k] * bia[cJ[m][k] * 16 + cout];
    d_Beff[co] = s;
  }
  if (idx >= 9 * 128 * 128) return;
  int ci = idx & 127;
  int co = (idx >> 7) & 127;
  int tap = idx >> 14;
  int cin = ci >> 3, k = ci & 7;
  int cout = co >> 3, m = co & 7;
  float v = cS[m][k] * W[((cJ[m][k] * 16 + cout) * 16 + cin) * 9 + tap];
  d_Wg[idx] = __float2half(v);
}

// ---------------------------------------------------------------------------
// Conv kernel. CTA per (b, 2 output rows). M=256, N=128, K=9x128 (16-ci chunks).
// 8 warps of 64x64. Double-buffered cp.async smem + double-buffered register
// fragments across taps. B smem rows padded to 48B -> conflict-free reads.
// ---------------------------------------------------------------------------
#define AROW 132
#define A_BYTES (4 * AROW * 48)        // 25344
#define B_STR 48                       // bytes per co row in smem (32B data)
#define B_BYTES (9 * 128 * B_STR)      // 55296
#define SM_TOTAL (2 * A_BYTES + 2 * B_BYTES)   // 161280

__global__ void __launch_bounds__(256, 1)
conv_kernel(float* __restrict__ out) {
  extern __shared__ __align__(128) unsigned char sh[];
  const uint32_t sA0 = smem_u32(sh);
  const uint32_t sB0 = sA0 + 2 * A_BYTES;
  uint32_t* sB32base = (uint32_t*)(sh + 2 * A_BYTES);

  const int tid = threadIdx.x, warp = tid >> 5, lane = tid & 31;
  const int h2 = blockIdx.x, b = blockIdx.y;
  const int h0 = h2 * 2;
  const int warpM = warp >> 1, warpN = warp & 1;
  const int hh = warpM >> 1, wq0 = (warpM & 1) * 64;
  const int g = lane >> 2, q = lane & 3;
  const int rsel = lane & 15, csel = lane >> 4;

  // zero both A buffers (halo slots / invalid h rows stay zero)
  {
    uint4 z = make_uint4(0, 0, 0, 0);
    uint4* p = (uint4*)sh;
    for (int i = tid; i < 2 * A_BYTES / 16; i += 256) p[i] = z;
  }
  __syncthreads();

  float acc[4][8][4];
#pragma unroll
  for (int i = 0; i < 4; i++)
#pragma unroll
    for (int j = 0; j < 8; j++)
#pragma unroll
      for (int t = 0; t < 4; t++) acc[i][j][t] = 0.f;

  auto issue = [&](int cc, int buf) {
    uint32_t aB = sA0 + buf * A_BYTES;
#pragma unroll
    for (int i = 0; i < 4; ++i) {
      int task = tid + i * 256;              // r(2b) | w(7b) | half(1b)
      int r = task >> 8;
      int w = (task >> 1) & 127;
      int half = task & 1;
      int gh = h0 - 1 + r;
      if ((unsigned)gh < (unsigned)HW) {
        const __half* src = d_x16 +
            (((size_t)(b * HW + gh) * HW + w) * CH + cc * 16 + half * 8);
        cp16(aB + (uint32_t)(r * AROW + w + 1) * 48 + half * 16, src);
      }
    }
    uint32_t bB = sB0 + buf * B_BYTES;
#pragma unroll
    for (int i = 0; i < 9; ++i) {
      int idx = tid + i * 256;               // tap | co | p2
      int p2 = idx & 1;
      int co = (idx >> 1) & 127;
      int tap = idx >> 8;
      const __half* src = d_Wg + ((tap * 128 + co) * 128 + cc * 16) + p2 * 8;
      cp16(bB + (uint32_t)(tap * 128 + co) * B_STR + p2 * 16, src);
    }
    cp_commit();
  };

  issue(0, 0);

  for (int c = 0; c < 8; ++c) {
    if (c < 7) issue(c + 1, (c + 1) & 1);
    if (c < 7) cp_wait1(); else cp_wait0();
    __syncthreads();

    const int buf = c & 1;
    const uint32_t aB = sA0 + buf * A_BYTES;
    const uint32_t* sBp = sB32base + buf * (B_BYTES / 4);

    uint32_t afr[2][4][4];
    uint32_t bfr[2][8][2];

    auto LF = [&](int tap, int pp) {
      const int dh = tap / 3, dw = tap % 3;
      uint32_t arow = aB + (uint32_t)((hh + dh) * AROW) * 48;
#pragma unroll
      for (int mf = 0; mf < 4; ++mf) {
        uint32_t addr = arow + (uint32_t)(wq0 + mf * 16 + dw + rsel) * 48
                        + csel * 16;
        asm volatile(
          "ldmatrix.sync.aligned.m8n8.x4.shared.b16 {%0,%1,%2,%3}, [%4];\n"
          : "=r"(afr[pp][mf][0]), "=r"(afr[pp][mf][1]),
            "=r"(afr[pp][mf][2]), "=r"(afr[pp][mf][3])
          : "r"(addr));
      }
      // B rows at 12-u32 stride: banks (g*12+q)&31 cover all 32 -> conflict-free
      const uint32_t* sbt = sBp + (size_t)tap * 128 * (B_STR / 4)
                            + (warpN * 64 + g) * (B_STR / 4);
#pragma unroll
      for (int nf = 0; nf < 8; ++nf) {
        const uint32_t* bp = sbt + nf * 8 * (B_STR / 4);
        bfr[pp][nf][0] = bp[q];
        bfr[pp][nf][1] = bp[q + 4];
      }
    };

    LF(0, 0);
#pragma unroll
    for (int tap = 0; tap < 9; ++tap) {
      const int cur = tap & 1, nxt = cur ^ 1;
      if (tap < 8) LF(tap + 1, nxt);
#pragma unroll
      for (int nf = 0; nf < 8; ++nf)
#pragma unroll
        for (int mf = 0; mf < 4; ++mf)
          asm volatile(
            "mma.sync.aligned.m16n8k16.row.col.f32.f16.f16.f32 "
            "{%0,%1,%2,%3}, {%4,%5,%6,%7}, {%8,%9}, {%0,%1,%2,%3};\n"
            : "+f"(acc[mf][nf][0]), "+f"(acc[mf][nf][1]),
              "+f"(acc[mf][nf][2]), "+f"(acc[mf][nf][3])
            : "r"(afr[cur][mf][0]), "r"(afr[cur][mf][1]),
              "r"(afr[cur][mf][2]), "r"(afr[cur][mf][3]),
              "r"(bfr[cur][nf][0]), "r"(bfr[cur][nf][1]));
    }
    __syncthreads();
  }

  // ---- epilogue: bias + direct stores ----
  const int h_out = h0 + hh;
  float* ob = out + ((size_t)(b * CH) * HW + h_out) * HW;
#pragma unroll
  for (int nf = 0; nf < 8; ++nf) {
    int co = warpN * 64 + nf * 8 + 2 * q;
    float b0 = d_Beff[co], b1 = d_Beff[co + 1];
    float* p0 = ob + (size_t)co * HW * HW;
    float* p1 = p0 + (size_t)HW * HW;
#pragma unroll
    for (int mf = 0; mf < 4; ++mf) {
      int w = wq0 + mf * 16 + g;
      p0[w]     = acc[mf][nf][0] + b0;
      p1[w]     = acc[mf][nf][1] + b1;
      p0[w + 8] = acc[mf][nf][2] + b0;
      p1[w + 8] = acc[mf][nf][3] + b1;
    }
  }
}

// ---------------------------------------------------------------------------
extern "C" void kernel_launch(void* const* d_in, const int* in_sizes, int n_in,
                              void* d_out, int out_size) {
  (void)in_sizes; (void)n_in; (void)out_size;
  const float* x = (const float*)d_in[0];
  const float* W = (const float*)d_in[1];
  const float* b = (const float*)d_in[2];
  float* out = (float*)d_out;

  dim3 gx(HW, NB);
  xprep_kernel<<<gx, 256>>>(x);
  weff_kernel<<<(9 * 128 * 128 + 255) / 256, 256>>>(W, b);

  cudaFuncSetAttribute(conv_kernel,
                       cudaFuncAttributeMaxDynamicSharedMemorySize, SM_TOTAL);
  dim3 grid(HW / 2, NB);
  conv_kernel<<<grid, 256, SM_TOTAL>>>(out);
}

// round 6
// speedup vs baseline: 1.0241x; 1.0241x over previous
#include <cuda_runtime.h>
#include <cuda_fp16.h>
#include <cstdint>

#define HW 128
#define CH 128
#define NB 8

// ---------------------------------------------------------------------------
// Device-global scratch
// ---------------------------------------------------------------------------
__device__ __align__(256) __half d_x16[(size_t)NB * HW * HW * CH];  // NHWC fp16
__device__ __align__(256) __half d_Wg[9 * 128 * 128];               // [tap][co][ci]
__device__ float d_Beff[128];

__constant__ int cJ[8][8] = {
  {0,1,2,3,4,5,6,7},{1,0,4,6,2,7,3,5},{2,4,0,5,1,3,7,6},{3,6,5,0,7,2,1,4},
  {4,2,1,7,0,6,5,3},{5,7,3,2,6,0,4,1},{6,3,7,1,5,4,0,2},{7,5,6,4,3,1,2,0}};
__constant__ float cS[8][8] = {
  { 1, 1, 1, 1,-1,-1,-1,-1},{ 1, 1,-1,-1, 1,-1, 1,-1},
  { 1, 1, 1,-1,-1, 1, 1, 1},{ 1, 1, 1, 1,-1,-1,-1,-1},
  { 1, 1,-1, 1, 1, 1,-1, 1},{ 1, 1, 1,-1,-1, 1, 1, 1},
  { 1, 1,-1,-1, 1,-1, 1,-1},{ 1, 1,-1, 1, 1, 1,-1, 1}};

__device__ __forceinline__ uint32_t smem_u32(const void* p) {
  uint32_t a;
  asm("{ .reg .u64 t; cvta.to.shared.u64 t, %1; cvt.u32.u64 %0, t; }"
      : "=r"(a) : "l"(p));
  return a;
}
__device__ __forceinline__ void cp16(uint32_t dst, const void* src) {
  asm volatile("cp.async.cg.shared.global [%0], [%1], 16;"
               :: "r"(dst), "l"(src) : "memory");
}
__device__ __forceinline__ void cp_commit() {
  asm volatile("cp.async.commit_group;" ::: "memory");
}
__device__ __forceinline__ void cp_wait1() {
  asm volatile("cp.async.wait_group 1;" ::: "memory");
}
__device__ __forceinline__ void cp_wait0() {
  asm volatile("cp.async.wait_group 0;" ::: "memory");
}

// ---------------------------------------------------------------------------
// Prepass 1: fp32 NCHW -> fp16 NHWC. 3-phase smem transpose, CTA per (h, b).
//   sm1 [ci][S1]  (phase-1 stores conflict-free)
//   sm2 [w][S2]   (phase-2a: lanes span w -> <=2-way; phase-2b conflict-free)
// ---------------------------------------------------------------------------
#define S1 132
#define S2 136
#define XPREP_SMEM ((128 * S1 + 128 * S2) * 2)   // 68608 bytes

__global__ void __launch_bounds__(256) xprep_kernel(const float* __restrict__ x) {
  extern __shared__ __align__(16) __half xsm[];
  __half* sm1 = xsm;               // [128][S1]
  __half* sm2 = xsm + 128 * S1;    // [128][S2]
  const int h = blockIdx.x, b = blockIdx.y, tid = threadIdx.x;
  const float* xp = x + ((size_t)b * CH) * HW * HW + (size_t)h * HW;

  // Phase 1: (ci, seg): read 64B contiguous, store [ci][w] halves.
#pragma unroll
  for (int i = 0; i < 4; ++i) {
    int t = tid + i * 256;
    int ci = t >> 3, seg = t & 7;
    const float4* src = (const float4*)(xp + (size_t)ci * HW * HW + seg * 16);
    float4 v0 = src[0], v1 = src[1], v2 = src[2], v3 = src[3];
    __half2* dst = (__half2*)(sm1 + ci * S1 + seg * 16);
    dst[0] = __floats2half2_rn(v0.x, v0.y);
    dst[1] = __floats2half2_rn(v0.z, v0.w);
    dst[2] = __floats2half2_rn(v1.x, v1.y);
    dst[3] = __floats2half2_rn(v1.z, v1.w);
    dst[4] = __floats2half2_rn(v2.x, v2.y);
    dst[5] = __floats2half2_rn(v2.z, v2.w);
    dst[6] = __floats2half2_rn(v3.x, v3.y);
    dst[7] = __floats2half2_rn(v3.z, v3.w);
  }
  __syncthreads();

  // Phase 2a: (w2, c8): read 8 half2 columns (lanes span w -> spread banks),
  // write two 16B rows of sm2.
#pragma unroll
  for (int i = 0; i < 4; ++i) {
    int t = tid + i * 256;
    int w2 = (t & 7) | (((t >> 5) & 7) << 3);     // 0..63
    int c8 = ((t >> 3) & 3) | ((t >> 8) << 2);    // 0..15
    int w = w2 * 2;
    __half lo[8], hi[8];
#pragma unroll
    for (int jj = 0; jj < 8; ++jj) {
      uint32_t v = *(const uint32_t*)(sm1 + (c8 * 8 + jj) * S1 + w);
      lo[jj] = __ushort_as_half((unsigned short)(v & 0xFFFF));
      hi[jj] = __ushort_as_half((unsigned short)(v >> 16));
    }
    *(uint4*)(sm2 + (size_t)w * S2 + c8 * 8)       = *(const uint4*)lo;
    *(uint4*)(sm2 + (size_t)(w + 1) * S2 + c8 * 8) = *(const uint4*)hi;
  }
  __syncthreads();

  // Phase 2b: coalesced 16B reads + coalesced NHWC stores.
  __half* op = d_x16 + ((size_t)(b * HW + h)) * HW * CH;
#pragma unroll
  for (int i = 0; i < 8; ++i) {
    int t = tid + i * 256;
    int c8 = t & 15;
    int w = ((t >> 4) & 1) | (((t >> 5)) << 1);
    uint4 u = *(const uint4*)(sm2 + (size_t)w * S2 + c8 * 8);
    *(uint4*)(op + (size_t)w * CH + c8 * 8) = u;
  }
}

// ---------------------------------------------------------------------------
// Prepass 2: fold signs into weights -> d_Wg[tap][co][ci] fp16; also bias.
// ---------------------------------------------------------------------------
__global__ void __launch_bounds__(256)
weff_kernel(const float* __restrict__ W, const float* __restrict__ bia) {
  int idx = blockIdx.x * 256 + threadIdx.x;
  if (blockIdx.x == 0 && threadIdx.x < 128) {
    int co = threadIdx.x, cout = co >> 3, m = co & 7;
    float s = 0.f;
#pragma unroll
    for (int k = 0; k < 8; k++) s += cS[m][k] * bia[cJ[m][k] * 16 + cout];
    d_Beff[co] = s;
  }
  if (idx >= 9 * 128 * 128) return;
  int ci = idx & 127;
  int co = (idx >> 7) & 127;
  int tap = idx >> 14;
  int cin = ci >> 3, k = ci & 7;
  int cout = co >> 3, m = co & 7;
  float v = cS[m][k] * W[((cJ[m][k] * 16 + cout) * 16 + cin) * 9 + tap];
  d_Wg[idx] = __float2half(v);
}

// ---------------------------------------------------------------------------
// Conv kernel. CTA per (b, 2 output rows). M=256, N=128, K=9x128 (16-ci chunks).
// 512 threads = 16 warps of 32x64 (4 warps/SMSP for latency hiding).
// Double-buffered cp.async smem; A-fragments double-buffered across taps.
// ---------------------------------------------------------------------------
#define AROW 132
#define A_BYTES (4 * AROW * 48)        // 25344
#define B_STR 48                       // bytes per co row in smem (32B data)
#define B_BYTES (9 * 128 * B_STR)      // 55296
#define SM_TOTAL (2 * A_BYTES + 2 * B_BYTES)   // 161280
#define NTHR 512

__global__ void __launch_bounds__(NTHR, 1)
conv_kernel(float* __restrict__ out) {
  extern __shared__ __align__(128) unsigned char sh[];
  const uint32_t sA0 = smem_u32(sh);
  const uint32_t sB0 = sA0 + 2 * A_BYTES;
  uint32_t* sB32base = (uint32_t*)(sh + 2 * A_BYTES);

  const int tid = threadIdx.x, warp = tid >> 5, lane = tid & 31;
  const int h2 = blockIdx.x, b = blockIdx.y;
  const int h0 = h2 * 2;
  const int warpM = warp >> 1, warpN = warp & 1;
  const int hh = warpM >> 2, wq0 = (warpM & 3) * 32;
  const int g = lane >> 2, q = lane & 3;
  const int rsel = lane & 15, csel = lane >> 4;

  // zero both A buffers (halo slots / invalid h rows stay zero)
  {
    uint4 z = make_uint4(0, 0, 0, 0);
    uint4* p = (uint4*)sh;
    for (int i = tid; i < 2 * A_BYTES / 16; i += NTHR) p[i] = z;
  }
  __syncthreads();

  float acc[2][8][4];
#pragma unroll
  for (int i = 0; i < 2; i++)
#pragma unroll
    for (int j = 0; j < 8; j++)
#pragma unroll
      for (int t = 0; t < 4; t++) acc[i][j][t] = 0.f;

  auto issue = [&](int cc, int buf) {
    uint32_t aB = sA0 + buf * A_BYTES;
#pragma unroll
    for (int i = 0; i < 2; ++i) {
      int task = tid + i * NTHR;             // r(2b) | w(7b) | half(1b)
      int r = task >> 8;
      int w = (task >> 1) & 127;
      int half = task & 1;
      int gh = h0 - 1 + r;
      if ((unsigned)gh < (unsigned)HW) {
        const __half* src = d_x16 +
            (((size_t)(b * HW + gh) * HW + w) * CH + cc * 16 + half * 8);
        cp16(aB + (uint32_t)(r * AROW + w + 1) * 48 + half * 16, src);
      }
    }
    uint32_t bB = sB0 + buf * B_BYTES;
#pragma unroll
    for (int i = 0; i < 5; ++i) {
      int idx = tid + i * NTHR;              // tap | co | p2  (2304 tasks)
      if (idx < 2304) {
        int p2 = idx & 1;
        int co = (idx >> 1) & 127;
        int tap = idx >> 8;
        const __half* src = d_Wg + ((tap * 128 + co) * 128 + cc * 16) + p2 * 8;
        cp16(bB + (uint32_t)(tap * 128 + co) * B_STR + p2 * 16, src);
      }
    }
    cp_commit();
  };

  issue(0, 0);

  for (int c = 0; c < 8; ++c) {
    if (c < 7) issue(c + 1, (c + 1) & 1);
    if (c < 7) cp_wait1(); else cp_wait0();
    __syncthreads();

    const int buf = c & 1;
    const uint32_t aB = sA0 + buf * A_BYTES;
    const uint32_t* sBp = sB32base + buf * (B_BYTES / 4);

    uint32_t afr[2][2][4];

    auto LFA = [&](int tap, int pp) {
      const int dh = tap / 3, dw = tap % 3;
      uint32_t arow = aB + (uint32_t)((hh + dh) * AROW) * 48;
#pragma unroll
      for (int mf = 0; mf < 2; ++mf) {
        uint32_t addr = arow + (uint32_t)(wq0 + mf * 16 + dw + rsel) * 48
                        + csel * 16;
        asm volatile(
          "ldmatrix.sync.aligned.m8n8.x4.shared.b16 {%0,%1,%2,%3}, [%4];\n"
          : "=r"(afr[pp][mf][0]), "=r"(afr[pp][mf][1]),
            "=r"(afr[pp][mf][2]), "=r"(afr[pp][mf][3])
          : "r"(addr));
      }
    };

    LFA(0, 0);
#pragma unroll
    for (int tap = 0; tap < 9; ++tap) {
      const int cur = tap & 1, nxt = cur ^ 1;
      // B fragments (conflict-free: banks (g*12+q)&31 cover all 32)
      uint32_t bfr[8][2];
      const uint32_t* sbt = sBp + (size_t)tap * 128 * (B_STR / 4)
                            + (warpN * 64 + g) * (B_STR / 4);
#pragma unroll
      for (int nf = 0; nf < 8; ++nf) {
        const uint32_t* bp = sbt + nf * 8 * (B_STR / 4);
        bfr[nf][0] = bp[q];
        bfr[nf][1] = bp[q + 4];
      }
      if (tap < 8) LFA(tap + 1, nxt);
#pragma unroll
      for (int nf = 0; nf < 8; ++nf)
#pragma unroll
        for (int mf = 0; mf < 2; ++mf)
          asm volatile(
            "mma.sync.aligned.m16n8k16.row.col.f32.f16.f16.f32 "
            "{%0,%1,%2,%3}, {%4,%5,%6,%7}, {%8,%9}, {%0,%1,%2,%3};\n"
            : "+f"(acc[mf][nf][0]), "+f"(acc[mf][nf][1]),
              "+f"(acc[mf][nf][2]), "+f"(acc[mf][nf][3])
            : "r"(afr[cur][mf][0]), "r"(afr[cur][mf][1]),
              "r"(afr[cur][mf][2]), "r"(afr[cur][mf][3]),
              "r"(bfr[nf][0]), "r"(bfr[nf][1]));
    }
    __syncthreads();
  }

  // ---- epilogue: bias + direct stores ----
  const int h_out = h0 + hh;
  float* ob = out + ((size_t)(b * CH) * HW + h_out) * HW;
#pragma unroll
  for (int nf = 0; nf < 8; ++nf) {
    int co = warpN * 64 + nf * 8 + 2 * q;
    float b0 = d_Beff[co], b1 = d_Beff[co + 1];
    float* p0 = ob + (size_t)co * HW * HW;
    float* p1 = p0 + (size_t)HW * HW;
#pragma unroll
    for (int mf = 0; mf < 2; ++mf) {
      int w = wq0 + mf * 16 + g;
      p0[w]     = acc[mf][nf][0] + b0;
      p1[w]     = acc[mf][nf][1] + b1;
      p0[w + 8] = acc[mf][nf][2] + b0;
      p1[w + 8] = acc[mf][nf][3] + b1;
    }
  }
}

// ---------------------------------------------------------------------------
extern "C" void kernel_launch(void* const* d_in, const int* in_sizes, int n_in,
                              void* d_out, int out_size) {
  (void)in_sizes; (void)n_in; (void)out_size;
  const float* x = (const float*)d_in[0];
  const float* W = (const float*)d_in[1];
  const float* b = (const float*)d_in[2];
  float* out = (float*)d_out;

  cudaFuncSetAttribute(xprep_kernel,
                       cudaFuncAttributeMaxDynamicSharedMemorySize, XPREP_SMEM);
  dim3 gx(HW, NB);
  xprep_kernel<<<gx, 256, XPREP_SMEM>>>(x);
  weff_kernel<<<(9 * 128 * 128 + 255) / 256, 256>>>(W, b);

  cudaFuncSetAttribute(conv_kernel,
                       cudaFuncAttributeMaxDynamicSharedMemorySize, SM_TOTAL);
  dim3 grid(HW / 2, NB);
  conv_kernel<<<grid, NTHR, SM_TOTAL>>>(out);
}

// round 7
// speedup vs baseline: 1.0467x; 1.0222x over previous
#include <cuda_runtime.h>
#include <cuda_fp16.h>
#include <cstdint>

#define HW 128
#define CH 128
#define NB 8

// ---------------------------------------------------------------------------
// Device-global scratch
// ---------------------------------------------------------------------------
__device__ __align__(256) __half d_x16[(size_t)NB * HW * HW * CH];  // NHWC fp16
__device__ __align__(256) __half d_Wg[9 * 128 * 128];               // [tap][co][ci]
__device__ float d_Beff[128];

__constant__ int cJ[8][8] = {
  {0,1,2,3,4,5,6,7},{1,0,4,6,2,7,3,5},{2,4,0,5,1,3,7,6},{3,6,5,0,7,2,1,4},
  {4,2,1,7,0,6,5,3},{5,7,3,2,6,0,4,1},{6,3,7,1,5,4,0,2},{7,5,6,4,3,1,2,0}};
__constant__ float cS[8][8] = {
  { 1, 1, 1, 1,-1,-1,-1,-1},{ 1, 1,-1,-1, 1,-1, 1,-1},
  { 1, 1, 1,-1,-1, 1, 1, 1},{ 1, 1, 1, 1,-1,-1,-1,-1},
  { 1, 1,-1, 1, 1, 1,-1, 1},{ 1, 1, 1,-1,-1, 1, 1, 1},
  { 1, 1,-1,-1, 1,-1, 1,-1},{ 1, 1,-1, 1, 1, 1,-1, 1}};

__device__ __forceinline__ uint32_t smem_u32(const void* p) {
  uint32_t a;
  asm("{ .reg .u64 t; cvta.to.shared.u64 t, %1; cvt.u32.u64 %0, t; }"
      : "=r"(a) : "l"(p));
  return a;
}
__device__ __forceinline__ void cp16(uint32_t dst, const void* src) {
  asm volatile("cp.async.cg.shared.global [%0], [%1], 16;"
               :: "r"(dst), "l"(src) : "memory");
}
__device__ __forceinline__ void cp_commit() {
  asm volatile("cp.async.commit_group;" ::: "memory");
}
__device__ __forceinline__ void cp_wait1() {
  asm volatile("cp.async.wait_group 1;" ::: "memory");
}
__device__ __forceinline__ void cp_wait0() {
  asm volatile("cp.async.wait_group 0;" ::: "memory");
}

// ---------------------------------------------------------------------------
// Prepass 1: fp32 NCHW -> fp16 NHWC. 3-phase smem transpose, CTA per (h, b).
// ---------------------------------------------------------------------------
#define S1 132
#define S2 136
#define XPREP_SMEM ((128 * S1 + 128 * S2) * 2)   // 68608 bytes

__global__ void __launch_bounds__(256) xprep_kernel(const float* __restrict__ x) {
  extern __shared__ __align__(16) __half xsm[];
  __half* sm1 = xsm;               // [128][S1]
  __half* sm2 = xsm + 128 * S1;    // [128][S2]
  const int h = blockIdx.x, b = blockIdx.y, tid = threadIdx.x;
  const float* xp = x + ((size_t)b * CH) * HW * HW + (size_t)h * HW;

#pragma unroll
  for (int i = 0; i < 4; ++i) {
    int t = tid + i * 256;
    int ci = t >> 3, seg = t & 7;
    const float4* src = (const float4*)(xp + (size_t)ci * HW * HW + seg * 16);
    float4 v0 = src[0], v1 = src[1], v2 = src[2], v3 = src[3];
    __half2* dst = (__half2*)(sm1 + ci * S1 + seg * 16);
    dst[0] = __floats2half2_rn(v0.x, v0.y);
    dst[1] = __floats2half2_rn(v0.z, v0.w);
    dst[2] = __floats2half2_rn(v1.x, v1.y);
    dst[3] = __floats2half2_rn(v1.z, v1.w);
    dst[4] = __floats2half2_rn(v2.x, v2.y);
    dst[5] = __floats2half2_rn(v2.z, v2.w);
    dst[6] = __floats2half2_rn(v3.x, v3.y);
    dst[7] = __floats2half2_rn(v3.z, v3.w);
  }
  __syncthreads();

#pragma unroll
  for (int i = 0; i < 4; ++i) {
    int t = tid + i * 256;
    int w2 = (t & 7) | (((t >> 5) & 7) << 3);     // 0..63
    int c8 = ((t >> 3) & 3) | ((t >> 8) << 2);    // 0..15
    int w = w2 * 2;
    __half lo[8], hi[8];
#pragma unroll
    for (int jj = 0; jj < 8; ++jj) {
      uint32_t v = *(const uint32_t*)(sm1 + (c8 * 8 + jj) * S1 + w);
      lo[jj] = __ushort_as_half((unsigned short)(v & 0xFFFF));
      hi[jj] = __ushort_as_half((unsigned short)(v >> 16));
    }
    *(uint4*)(sm2 + (size_t)w * S2 + c8 * 8)       = *(const uint4*)lo;
    *(uint4*)(sm2 + (size_t)(w + 1) * S2 + c8 * 8) = *(const uint4*)hi;
  }
  __syncthreads();

  __half* op = d_x16 + ((size_t)(b * HW + h)) * HW * CH;
#pragma unroll
  for (int i = 0; i < 8; ++i) {
    int t = tid + i * 256;
    int c8 = t & 15;
    int w = ((t >> 4) & 1) | (((t >> 5)) << 1);
    uint4 u = *(const uint4*)(sm2 + (size_t)w * S2 + c8 * 8);
    *(uint4*)(op + (size_t)w * CH + c8 * 8) = u;
  }
}

// ---------------------------------------------------------------------------
// Prepass 2: fold signs into weights -> d_Wg[tap][co][ci] fp16; also bias.
// ---------------------------------------------------------------------------
__global__ void __launch_bounds__(256)
weff_kernel(const float* __restrict__ W, const float* __restrict__ bia) {
  int idx = blockIdx.x * 256 + threadIdx.x;
  if (blockIdx.x == 0 && threadIdx.x < 128) {
    int co = threadIdx.x, cout = co >> 3, m = co & 7;
    float s = 0.f;
#pragma unroll
    for (int k = 0; k < 8; k++) s += cS[m][k] * bia[cJ[m][k] * 16 + cout];
    d_Beff[co] = s;
  }
  if (idx >= 9 * 128 * 128) return;
  int ci = idx & 127;
  int co = (idx >> 7) & 127;
  int tap = idx >> 14;
  int cin = ci >> 3, k = ci & 7;
  int cout = co >> 3, m = co & 7;
  float v = cS[m][k] * W[((cJ[m][k] * 16 + cout) * 16 + cin) * 9 + tap];
  d_Wg[idx] = __float2half(v);
}

// ---------------------------------------------------------------------------
// Conv kernel. CTA per (b, 2 output rows). M=256, N=128, K=9x128 (16-ci chunks).
// 512 threads = 16 warps of 32x64 (4 warps/SMSP). Double-buffered cp.async
// smem; A fragments double-buffered across taps; B via conflict-free
// ldmatrix.x4 on 48B-strided rows.
// ---------------------------------------------------------------------------
#define AROW 132
#define A_BYTES (4 * AROW * 48)        // 25344
#define B_STR 48                       // bytes per co row in smem (32B data)
#define B_BYTES (9 * 128 * B_STR)      // 55296
#define SM_TOTAL (2 * A_BYTES + 2 * B_BYTES)   // 161280
#define NTHR 512

__global__ void __launch_bounds__(NTHR, 1)
conv_kernel(float* __restrict__ out) {
  extern __shared__ __align__(128) unsigned char sh[];
  const uint32_t sA0 = smem_u32(sh);
  const uint32_t sB0 = sA0 + 2 * A_BYTES;

  const int tid = threadIdx.x, warp = tid >> 5, lane = tid & 31;
  const int h2 = blockIdx.x, b = blockIdx.y;
  const int h0 = h2 * 2;
  const int warpM = warp >> 1, warpN = warp & 1;
  const int hh = warpM >> 2, wq0 = (warpM & 3) * 32;
  const int g = lane >> 2, q = lane & 3;
  const int rsel = lane & 15, csel = lane >> 4;
  const int mrow = lane & 7, mid = lane >> 3;     // ldmatrix-B addressing

  // zero both A buffers (halo slots / invalid h rows stay zero)
  {
    uint4 z = make_uint4(0, 0, 0, 0);
    uint4* p = (uint4*)sh;
    for (int i = tid; i < 2 * A_BYTES / 16; i += NTHR) p[i] = z;
  }
  __syncthreads();

  float acc[2][8][4];
#pragma unroll
  for (int i = 0; i < 2; i++)
#pragma unroll
    for (int j = 0; j < 8; j++)
#pragma unroll
      for (int t = 0; t < 4; t++) acc[i][j][t] = 0.f;

  auto issue = [&](int cc, int buf) {
    uint32_t aB = sA0 + buf * A_BYTES;
#pragma unroll
    for (int i = 0; i < 2; ++i) {
      int task = tid + i * NTHR;             // r(2b) | w(7b) | half(1b)
      int r = task >> 8;
      int w = (task >> 1) & 127;
      int half = task & 1;
      int gh = h0 - 1 + r;
      if ((unsigned)gh < (unsigned)HW) {
        const __half* src = d_x16 +
            (((size_t)(b * HW + gh) * HW + w) * CH + cc * 16 + half * 8);
        cp16(aB + (uint32_t)(r * AROW + w + 1) * 48 + half * 16, src);
      }
    }
    uint32_t bB = sB0 + buf * B_BYTES;
#pragma unroll
    for (int i = 0; i < 5; ++i) {
      int idx = tid + i * NTHR;              // tap | co | p2  (2304 tasks)
      if (idx < 2304) {
        int p2 = idx & 1;
        int co = (idx >> 1) & 127;
        int tap = idx >> 8;
        const __half* src = d_Wg + ((tap * 128 + co) * 128 + cc * 16) + p2 * 8;
        cp16(bB + (uint32_t)(tap * 128 + co) * B_STR + p2 * 16, src);
      }
    }
    cp_commit();
  };

  issue(0, 0);

  for (int c = 0; c < 8; ++c) {
    if (c < 7) issue(c + 1, (c + 1) & 1);
    if (c < 7) cp_wait1(); else cp_wait0();
    __syncthreads();

    const int buf = c & 1;
    const uint32_t aB = sA0 + buf * A_BYTES;
    const uint32_t bB = sB0 + buf * B_BYTES;

    uint32_t afr[2][2][4];

    auto LFA = [&](int tap, int pp) {
      const int dh = tap / 3, dw = tap % 3;
      uint32_t arow = aB + (uint32_t)((hh + dh) * AROW) * 48;
#pragma unroll
      for (int mf = 0; mf < 2; ++mf) {
        uint32_t addr = arow + (uint32_t)(wq0 + mf * 16 + dw + rsel) * 48
                        + csel * 16;
        asm volatile(
          "ldmatrix.sync.aligned.m8n8.x4.shared.b16 {%0,%1,%2,%3}, [%4];\n"
          : "=r"(afr[pp][mf][0]), "=r"(afr[pp][mf][1]),
            "=r"(afr[pp][mf][2]), "=r"(afr[pp][mf][3])
          : "r"(addr));
      }
    };

    LFA(0, 0);
#pragma unroll
    for (int tap = 0; tap < 9; ++tap) {
      const int cur = tap & 1, nxt = cur ^ 1;
      // B fragments via ldmatrix.x4: rows at 48B stride -> conflict-free.
      // x4 #p covers nf = 2p (matrices 0,1 = k0-7,k8-15) and nf = 2p+1 (2,3).
      uint32_t bfr[8][2];
      uint32_t btap = bB + (uint32_t)tap * 128 * B_STR
                      + (uint32_t)(warpN * 64) * B_STR;
#pragma unroll
      for (int p = 0; p < 4; ++p) {
        uint32_t addr = btap
            + (uint32_t)((p * 2 + (mid >> 1)) * 8 + mrow) * B_STR
            + (mid & 1) * 16;
        asm volatile(
          "ldmatrix.sync.aligned.m8n8.x4.shared.b16 {%0,%1,%2,%3}, [%4];\n"
          : "=r"(bfr[p * 2][0]), "=r"(bfr[p * 2][1]),
            "=r"(bfr[p * 2 + 1][0]), "=r"(bfr[p * 2 + 1][1])
          : "r"(addr));
      }
      if (tap < 8) LFA(tap + 1, nxt);
#pragma unroll
      for (int nf = 0; nf < 8; ++nf)
#pragma unroll
        for (int mf = 0; mf < 2; ++mf)
          asm volatile(
            "mma.sync.aligned.m16n8k16.row.col.f32.f16.f16.f32 "
            "{%0,%1,%2,%3}, {%4,%5,%6,%7}, {%8,%9}, {%0,%1,%2,%3};\n"
            : "+f"(acc[mf][nf][0]), "+f"(acc[mf][nf][1]),
              "+f"(acc[mf][nf][2]), "+f"(acc[mf][nf][3])
            : "r"(afr[cur][mf][0]), "r"(afr[cur][mf][1]),
              "r"(afr[cur][mf][2]), "r"(afr[cur][mf][3]),
              "r"(bfr[nf][0]), "r"(bfr[nf][1]));
    }
    __syncthreads();
  }

  // ---- epilogue: bias + direct stores ----
  const int h_out = h0 + hh;
  float* ob = out + ((size_t)(b * CH) * HW + h_out) * HW;
#pragma unroll
  for (int nf = 0; nf < 8; ++nf) {
    int co = warpN * 64 + nf * 8 + 2 * q;
    float b0 = d_Beff[co], b1 = d_Beff[co + 1];
    float* p0 = ob + (size_t)co * HW * HW;
    float* p1 = p0 + (size_t)HW * HW;
#pragma unroll
    for (int mf = 0; mf < 2; ++mf) {
      int w = wq0 + mf * 16 + g;
      p0[w]     = acc[mf][nf][0] + b0;
      p1[w]     = acc[mf][nf][1] + b1;
      p0[w + 8] = acc[mf][nf][2] + b0;
      p1[w + 8] = acc[mf][nf][3] + b1;
    }
  }
}

// ---------------------------------------------------------------------------
extern "C" void kernel_launch(void* const* d_in, const int* in_sizes, int n_in,
                              void* d_out, int out_size) {
  (void)in_sizes; (void)n_in; (void)out_size;
  const float* x = (const float*)d_in[0];
  const float* W = (const float*)d_in[1];
  const float* b = (const float*)d_in[2];
  float* out = (float*)d_out;

  cudaFuncSetAttribute(xprep_kernel,
                       cudaFuncAttributeMaxDynamicSharedMemorySize, XPREP_SMEM);
  dim3 gx(HW, NB);
  xprep_kernel<<<gx, 256, XPREP_SMEM>>>(x);
  weff_kernel<<<(9 * 128 * 128 + 255) / 256, 256>>>(W, b);

  cudaFuncSetAttribute(conv_kernel,
                       cudaFuncAttributeMaxDynamicSharedMemorySize, SM_TOTAL);
  dim3 grid(HW / 2, NB);
  conv_kernel<<<grid, NTHR, SM_TOTAL>>>(out);
}

// round 8
// speedup vs baseline: 1.1136x; 1.0639x over previous
#include <cuda_runtime.h>
#include <cuda_fp16.h>
#include <cstdint>

#define HW 128
#define CH 128
#define NB 8

// ---------------------------------------------------------------------------
// Device-global scratch
// ---------------------------------------------------------------------------
__device__ __align__(256) __half d_x16[(size_t)NB * HW * HW * CH];  // NHWC fp16
// Winograd-transformed weights, laid out in exact mma B-fragment order:
// [cc 8][nu 16][wN 4][lane 32][8 u32]  (u32 = half2 (k, k+1))
__device__ __align__(256) uint32_t d_WU[8 * 16 * 4 * 32 * 8];       // 512KB
__device__ float d_Beff[128];

__constant__ int cJ[8][8] = {
  {0,1,2,3,4,5,6,7},{1,0,4,6,2,7,3,5},{2,4,0,5,1,3,7,6},{3,6,5,0,7,2,1,4},
  {4,2,1,7,0,6,5,3},{5,7,3,2,6,0,4,1},{6,3,7,1,5,4,0,2},{7,5,6,4,3,1,2,0}};
__constant__ float cS[8][8] = {
  { 1, 1, 1, 1,-1,-1,-1,-1},{ 1, 1,-1,-1, 1,-1, 1,-1},
  { 1, 1, 1,-1,-1, 1, 1, 1},{ 1, 1, 1, 1,-1,-1,-1,-1},
  { 1, 1,-1, 1, 1, 1,-1, 1},{ 1, 1, 1,-1,-1, 1, 1, 1},
  { 1, 1,-1,-1, 1,-1, 1,-1},{ 1, 1,-1, 1, 1, 1,-1, 1}};

__device__ __forceinline__ uint32_t smem_u32(const void* p) {
  uint32_t a;
  asm("{ .reg .u64 t; cvta.to.shared.u64 t, %1; cvt.u32.u64 %0, t; }"
      : "=r"(a) : "l"(p));
  return a;
}
__device__ __forceinline__ void cp16(uint32_t dst, const void* src) {
  asm volatile("cp.async.cg.shared.global [%0], [%1], 16;"
               :: "r"(dst), "l"(src) : "memory");
}
__device__ __forceinline__ void cp_commit() {
  asm volatile("cp.async.commit_group;" ::: "memory");
}
__device__ __forceinline__ void cp_wait1() {
  asm volatile("cp.async.wait_group 1;" ::: "memory");
}
__device__ __forceinline__ void cp_wait0() {
  asm volatile("cp.async.wait_group 0;" ::: "memory");
}

// ---------------------------------------------------------------------------
// Prepass 1: fp32 NCHW -> fp16 NHWC (unchanged from round 7).
// ---------------------------------------------------------------------------
#define S1 132
#define S2 136
#define XPREP_SMEM ((128 * S1 + 128 * S2) * 2)

__global__ void __launch_bounds__(256) xprep_kernel(const float* __restrict__ x) {
  extern __shared__ __align__(16) __half xsm[];
  __half* sm1 = xsm;
  __half* sm2 = xsm + 128 * S1;
  const int h = blockIdx.x, b = blockIdx.y, tid = threadIdx.x;
  const float* xp = x + ((size_t)b * CH) * HW * HW + (size_t)h * HW;

#pragma unroll
  for (int i = 0; i < 4; ++i) {
    int t = tid + i * 256;
    int ci = t >> 3, seg = t & 7;
    const float4* src = (const float4*)(xp + (size_t)ci * HW * HW + seg * 16);
    float4 v0 = src[0], v1 = src[1], v2 = src[2], v3 = src[3];
    __half2* dst = (__half2*)(sm1 + ci * S1 + seg * 16);
    dst[0] = __floats2half2_rn(v0.x, v0.y);
    dst[1] = __floats2half2_rn(v0.z, v0.w);
    dst[2] = __floats2half2_rn(v1.x, v1.y);
    dst[3] = __floats2half2_rn(v1.z, v1.w);
    dst[4] = __floats2half2_rn(v2.x, v2.y);
    dst[5] = __floats2half2_rn(v2.z, v2.w);
    dst[6] = __floats2half2_rn(v3.x, v3.y);
    dst[7] = __floats2half2_rn(v3.z, v3.w);
  }
  __syncthreads();

#pragma unroll
  for (int i = 0; i < 4; ++i) {
    int t = tid + i * 256;
    int w2 = (t & 7) | (((t >> 5) & 7) << 3);
    int c8 = ((t >> 3) & 3) | ((t >> 8) << 2);
    int w = w2 * 2;
    __half lo[8], hi[8];
#pragma unroll
    for (int jj = 0; jj < 8; ++jj) {
      uint32_t v = *(const uint32_t*)(sm1 + (c8 * 8 + jj) * S1 + w);
      lo[jj] = __ushort_as_half((unsigned short)(v & 0xFFFF));
      hi[jj] = __ushort_as_half((unsigned short)(v >> 16));
    }
    *(uint4*)(sm2 + (size_t)w * S2 + c8 * 8)       = *(const uint4*)lo;
    *(uint4*)(sm2 + (size_t)(w + 1) * S2 + c8 * 8) = *(const uint4*)hi;
  }
  __syncthreads();

  __half* op = d_x16 + ((size_t)(b * HW + h)) * HW * CH;
#pragma unroll
  for (int i = 0; i < 8; ++i) {
    int t = tid + i * 256;
    int c8 = t & 15;
    int w = ((t >> 4) & 1) | (((t >> 5)) << 1);
    uint4 u = *(const uint4*)(sm2 + (size_t)w * S2 + c8 * 8);
    *(uint4*)(op + (size_t)w * CH + c8 * 8) = u;
  }
}

// ---------------------------------------------------------------------------
// Prepass 2: GA3-fold + Winograd weight transform U = G (s*W) G^T,
// stored in B-fragment order. One thread per (co, ci-pair). Also bias.
// ---------------------------------------------------------------------------
__global__ void __launch_bounds__(256)
wu_kernel(const float* __restrict__ W, const float* __restrict__ bia) {
  int t = blockIdx.x * 256 + threadIdx.x;          // 0..8191
  if (blockIdx.x == 0 && threadIdx.x < 128) {
    int co = threadIdx.x, cout = co >> 3, m = co & 7;
    float s = 0.f;
#pragma unroll
    for (int k = 0; k < 8; k++) s += cS[m][k] * bia[cJ[m][k] * 16 + cout];
    d_Beff[co] = s;
  }
  if (t >= 128 * 64) return;
  int co = t >> 6, cp = t & 63;
  int m = co & 7, cout = co >> 3;

  float U2[2][16];
#pragma unroll
  for (int s2 = 0; s2 < 2; ++s2) {
    int ci = cp * 2 + s2;
    int cin = ci >> 3, k = ci & 7;
    float sg = cS[m][k];
    const float* wp = W + ((cJ[m][k] * 16 + cout) * 16 + cin) * 9;
    float w[3][3];
#pragma unroll
    for (int r = 0; r < 3; ++r)
#pragma unroll
      for (int c = 0; c < 3; ++c) w[r][c] = sg * wp[r * 3 + c];
    float Gw[4][3];
#pragma unroll
    for (int c = 0; c < 3; ++c) {
      Gw[0][c] = w[0][c];
      Gw[1][c] = 0.5f * (w[0][c] + w[1][c] + w[2][c]);
      Gw[2][c] = 0.5f * (w[0][c] - w[1][c] + w[2][c]);
      Gw[3][c] = w[2][c];
    }
#pragma unroll
    for (int i = 0; i < 4; ++i) {
      U2[s2][i * 4 + 0] = Gw[i][0];
      U2[s2][i * 4 + 1] = 0.5f * (Gw[i][0] + Gw[i][1] + Gw[i][2]);
      U2[s2][i * 4 + 2] = 0.5f * (Gw[i][0] - Gw[i][1] + Gw[i][2]);
      U2[s2][i * 4 + 3] = Gw[i][2];
    }
  }
  int cc = cp >> 3;
  int bi = (cp >> 2) & 1;
  int q = cp & 3;
  int l = (co & 7) * 4 + q;
  int wN = co >> 5;
  int f = (co >> 3) & 3;
#pragma unroll
  for (int nu = 0; nu < 16; ++nu) {
    __half2 hv = __floats2half2_rn(U2[0][nu], U2[1][nu]);
    d_WU[(((cc * 16 + nu) * 4 + wN) * 32 + l) * 8 + f * 2 + bi] =
        *(uint32_t*)&hv;
  }
}

// ---------------------------------------------------------------------------
// Winograd conv kernel. CTA per (b, tile-row th): 64 tiles of 2x2 outputs,
// N=128 co, K = 128 ci in 8 chunks of 16. 512 threads = 16 warps (4M x 4N),
// warp GEMM tile per point: m16 (16 tiles) x n32.
// ---------------------------------------------------------------------------
#define AROW 132
#define A_BYTES (4 * AROW * 48)        // 25344
#define V_BYTES (16 * 64 * 48)         // 49152
#define SM_TOTAL (2 * A_BYTES + V_BYTES)  // 99840
#define NTHR 512

__global__ void __launch_bounds__(NTHR, 1)
conv_wino(float* __restrict__ out) {
  extern __shared__ __align__(128) unsigned char sh[];
  const uint32_t sA0 = smem_u32(sh);
  const uint32_t sV  = sA0 + 2 * A_BYTES;

  const int tid = threadIdx.x, warp = tid >> 5, lane = tid & 31;
  const int th = blockIdx.x, b = blockIdx.y;
  const int h0 = th * 2;
  const int wM = warp >> 2, wN = warp & 3;
  const int g = lane >> 2, q = lane & 3;
  const int rsel = lane & 15, csel = lane >> 4;

  // zero both A buffers once (halo + invalid rows stay zero)
  {
    uint4 z = make_uint4(0, 0, 0, 0);
    uint4* p = (uint4*)sh;
    for (int i = tid; i < 2 * A_BYTES / 16; i += NTHR) p[i] = z;
  }
  __syncthreads();

  // [f][gi][x][ji][y]
  float outacc[4][2][2][2][2];
#pragma unroll
  for (int f = 0; f < 4; ++f)
#pragma unroll
    for (int i1 = 0; i1 < 2; ++i1)
#pragma unroll
      for (int i2 = 0; i2 < 2; ++i2)
#pragma unroll
        for (int i3 = 0; i3 < 2; ++i3)
#pragma unroll
          for (int i4 = 0; i4 < 2; ++i4) outacc[f][i1][i2][i3][i4] = 0.f;

  auto issueA = [&](int cc, int buf) {
    uint32_t aB = sA0 + buf * A_BYTES;
#pragma unroll
    for (int i = 0; i < 2; ++i) {
      int task = tid + i * NTHR;             // r(2b) | w(7b) | half(1b)
      int r = task >> 8;
      int w = (task >> 1) & 127;
      int half = task & 1;
      int gh = h0 - 1 + r;
      if ((unsigned)gh < (unsigned)HW) {
        const __half* src = d_x16 +
            (((size_t)(b * HW + gh) * HW + w) * CH + cc * 16 + half * 8);
        cp16(aB + (uint32_t)(r * AROW + w + 1) * 48 + half * 16, src);
      }
    }
    cp_commit();
  };

  issueA(0, 0);

  for (int c = 0; c < 8; ++c) {
    if (c < 7) issueA(c + 1, (c + 1) & 1);
    if (c < 7) cp_wait1(); else cp_wait0();
    __syncthreads();     // also: everyone done reading sV from prev chunk

    // ---- input transform: V = B^T d B, item = (tile tw, ci-pair cp) ----
    {
      const uint32_t aB = sA0 + (c & 1) * A_BYTES;
      int tw = tid >> 3, cp = tid & 7;
      uint32_t base = aB + (uint32_t)(2 * tw) * 48 + cp * 4;
      __half2 te[4][4];
#pragma unroll
      for (int j = 0; j < 4; ++j) {
        __half2 d0 = *(const __half2*)(sh + (base - sA0) + (0 * AROW + j) * 48);
        __half2 d1 = *(const __half2*)(sh + (base - sA0) + (1 * AROW + j) * 48);
        __half2 d2 = *(const __half2*)(sh + (base - sA0) + (2 * AROW + j) * 48);
        __half2 d3 = *(const __half2*)(sh + (base - sA0) + (3 * AROW + j) * 48);
        te[0][j] = __hsub2(d0, d2);
        te[1][j] = __hadd2(d1, d2);
        te[2][j] = __hsub2(d2, d1);
        te[3][j] = __hsub2(d1, d3);
      }
#pragma unroll
      for (int i = 0; i < 4; ++i) {
        __half2 v0 = __hsub2(te[i][0], te[i][2]);
        __half2 v1 = __hadd2(te[i][1], te[i][2]);
        __half2 v2 = __hsub2(te[i][2], te[i][1]);
        __half2 v3 = __hsub2(te[i][1], te[i][3]);
        uint32_t vb = (uint32_t)(((i * 4) * 64 + tw) * 48 + cp * 4);
        *(__half2*)(sh + 2 * A_BYTES + vb)            = v0;
        *(__half2*)(sh + 2 * A_BYTES + vb + 64 * 48)  = v1;
        *(__half2*)(sh + 2 * A_BYTES + vb + 128 * 48) = v2;
        *(__half2*)(sh + 2 * A_BYTES + vb + 192 * 48) = v3;
      }
    }
    __syncthreads();

    // ---- per-point GEMM + fold ----
    const uint4* wbase = (const uint4*)d_WU + ((c * 16) * 4 + wN) * 64 + lane * 2;
    uint4 wlo = wbase[0], whi = wbase[1];

    const float AT0[4] = {1.f, 1.f, 1.f, 0.f};
    const float AT1[4] = {0.f, 1.f, -1.f, -1.f};
    const float fz = 0.f;

#pragma unroll
    for (int nu = 0; nu < 16; ++nu) {
      const int nur = nu >> 2, nuc = nu & 3;

      // A fragment from V[nu]
      uint32_t a0, a1, a2, a3;
      {
        uint32_t addr = sV + (uint32_t)((nu * 64 + wM * 16 + rsel) * 48)
                        + csel * 16;
        asm volatile(
          "ldmatrix.sync.aligned.m8n8.x4.shared.b16 {%0,%1,%2,%3}, [%4];\n"
          : "=r"(a0), "=r"(a1), "=r"(a2), "=r"(a3) : "r"(addr));
      }

      // prefetch next nu's W
      uint4 nlo, nhi;
      if (nu < 15) {
        const uint4* np = (const uint4*)d_WU
            + (((c * 16 + nu + 1) * 4 + wN) * 32 + lane) * 2;
        nlo = np[0]; nhi = np[1];
      }

      uint32_t bfr[4][2] = {
        {wlo.x, wlo.y}, {wlo.z, wlo.w}, {whi.x, whi.y}, {whi.z, whi.w}};

      float macc[4][4];
#pragma unroll
      for (int f = 0; f < 4; ++f)
        asm volatile(
          "mma.sync.aligned.m16n8k16.row.col.f32.f16.f16.f32 "
          "{%0,%1,%2,%3}, {%4,%5,%6,%7}, {%8,%9}, {%10,%10,%10,%10};\n"
          : "=f"(macc[f][0]), "=f"(macc[f][1]),
            "=f"(macc[f][2]), "=f"(macc[f][3])
          : "r"(a0), "r"(a1), "r"(a2), "r"(a3),
            "r"(bfr[f][0]), "r"(bfr[f][1]), "f"(fz));

      // fold: out[x][y] += AT[x][nur]*AT[y][nuc]*m
#pragma unroll
      for (int f = 0; f < 4; ++f)
#pragma unroll
        for (int gi = 0; gi < 2; ++gi)
#pragma unroll
          for (int ji = 0; ji < 2; ++ji) {
            float mval = macc[f][gi * 2 + ji];
#pragma unroll
            for (int x = 0; x < 2; ++x) {
              float cx = (x == 0) ? AT0[nur] : AT1[nur];
              if (cx == 0.f) continue;
#pragma unroll
              for (int y = 0; y < 2; ++y) {
                float cy = (y == 0) ? AT0[nuc] : AT1[nuc];
                if (cy == 0.f) continue;
                outacc[f][gi][x][ji][y] += (cx * cy) * mval;
              }
            }
          }

      if (nu < 15) { wlo = nlo; whi = nhi; }
    }
  }

  // ---- epilogue: bias + float2 stores ----
#pragma unroll
  for (int f = 0; f < 4; ++f) {
#pragma unroll
    for (int ji = 0; ji < 2; ++ji) {
      int co = wN * 32 + f * 8 + 2 * q + ji;
      float be = d_Beff[co];
      float* ob = out + ((size_t)(b * CH + co)) * HW * HW;
#pragma unroll
      for (int gi = 0; gi < 2; ++gi) {
        int twp = wM * 16 + g + gi * 8;
#pragma unroll
        for (int x = 0; x < 2; ++x) {
          int hrow = h0 + x;
          float2 v;
          v.x = outacc[f][gi][x][ji][0] + be;
          v.y = outacc[f][gi][x][ji][1] + be;
          *(float2*)(ob + (size_t)hrow * HW + 2 * twp) = v;
        }
      }
    }
  }
}

// ---------------------------------------------------------------------------
extern "C" void kernel_launch(void* const* d_in, const int* in_sizes, int n_in,
                              void* d_out, int out_size) {
  (void)in_sizes; (void)n_in; (void)out_size;
  const float* x = (const float*)d_in[0];
  const float* W = (const float*)d_in[1];
  const float* b = (const float*)d_in[2];
  float* out = (float*)d_out;

  cudaFuncSetAttribute(xprep_kernel,
                       cudaFuncAttributeMaxDynamicSharedMemorySize, XPREP_SMEM);
  dim3 gx(HW, NB);
  xprep_kernel<<<gx, 256, XPREP_SMEM>>>(x);
  wu_kernel<<<32, 256>>>(W, b);

  cudaFuncSetAttribute(conv_wino,
                       cudaFuncAttributeMaxDynamicSharedMemorySize, SM_TOTAL);
  dim3 grid(64, NB);   // (tile-row, b)
  conv_wino<<<grid, NTHR, SM_TOTAL>>>(out);
}